// round 13
// baseline (speedup 1.0000x reference)
#include <cuda_runtime.h>

// BSplineTransformation: x (16,3,1024,1024) f32, control_points (1,2,35,35) f32
// out = concat(transformed (16,3,1024,1024), deformation_field (2,1024,1024))

#define HH 1024
#define WW 1024
#define NPIX (HH*WW)
#define NB 16
#define NC 3
#define NIMG (NB*NC)
#define CP 35
#define CP2 (CP*CP)

__device__ __forceinline__ void prefetch_l2(const void* p) {
    asm volatile("prefetch.global.L2 [%0];" :: "l"(p));
}

__global__ __launch_bounds__(256) void bspline_kernel(
    const float* __restrict__ x,
    const float* __restrict__ cp,
    float* __restrict__ out)
{
    __shared__ float scp[2*CP2];
    for (int t = threadIdx.x; t < 2*CP2; t += 256) scp[t] = cp[t];
    __syncthreads();

    const int p = blockIdx.x * 256 + threadIdx.x;   // pixel index; thread does ALL 48 images
    const int i = p >> 10;
    const int j = p & 1023;

    const float gy = fmaf((float)i, 2.0f / 1023.0f, -1.0f);
    const float gx = fmaf((float)j, 2.0f / 1023.0f, -1.0f);

    // ---- deformation field: grid_sample(control_points, border, align_corners) ----
    const float cx = (gx + 1.0f) * 17.0f;
    const float cy = (gy + 1.0f) * 17.0f;
    float icx = fminf(fmaxf((cx + 1.0f) * 17.0f, 0.0f), 34.0f);
    float icy = fminf(fmaxf((cy + 1.0f) * 17.0f, 0.0f), 34.0f);
    const float fcx = floorf(icx);
    const float fcy = floorf(icy);
    const int cx0 = (int)fcx;
    const int cy0 = (int)fcy;
    const int cx1 = min(cx0 + 1, CP - 1);
    const int cy1 = min(cy0 + 1, CP - 1);
    const float wx = icx - fcx;
    const float wy = icy - fcy;

    const int o00 = cy0 * CP + cx0;
    const int o01 = cy0 * CP + cx1;
    const int o10 = cy1 * CP + cx0;
    const int o11 = cy1 * CP + cx1;

    const float t0 = fmaf(wx, scp[o01] - scp[o00], scp[o00]);
    const float b0 = fmaf(wx, scp[o11] - scp[o10], scp[o10]);
    const float d0 = fmaf(wy, b0 - t0, t0);
    const float t1 = fmaf(wx, scp[CP2+o01] - scp[CP2+o00], scp[CP2+o00]);
    const float b1 = fmaf(wx, scp[CP2+o11] - scp[CP2+o10], scp[CP2+o10]);
    const float d1 = fmaf(wy, b1 - t1, t1);

    // deformation field output (once per pixel)
    {
        float* def = out + (long long)NIMG * NPIX;
        def[p]        = d0;
        def[NPIX + p] = d1;
    }

    // ---- main sample coords (shared by all 48 images) ----
    float sx = fminf(fmaxf((gx + d1 + 1.0f) * 511.5f, 0.0f), 1023.0f);
    float sy = fminf(fmaxf((gy + d0 + 1.0f) * 511.5f, 0.0f), 1023.0f);
    const float fsx = floorf(sx);
    const float fsy = floorf(sy);
    const int ix0 = (int)fsx;
    const int iy0 = (int)fsy;
    const int ix1 = min(ix0 + 1, WW - 1);
    const int iy1 = min(iy0 + 1, HH - 1);
    const float ax = sx - fsx;
    const float ay = sy - fsy;

    const int q00 = (iy0 << 10) + ix0;
    const int q01 = (iy0 << 10) + ix1;
    const int q10 = (iy1 << 10) + ix0;
    const int q11 = (iy1 << 10) + ix1;

    // prefetch image 0's lines (cold start) — harmless overlap with setup above
    prefetch_l2(x + q00);
    prefetch_l2(x + q01);
    prefetch_l2(x + q10);
    prefetch_l2(x + q11);

    // ---- 48 images: demand loads for image m, L2-prefetch for image m+1 ----
    const float* im = x;
    float*       ob = out + p;

    #pragma unroll
    for (int m = 0; m < NIMG; m++) {
        if (m + 1 < NIMG) {
            const float* nx = im + NPIX;
            prefetch_l2(nx + q00);
            prefetch_l2(nx + q01);
            prefetch_l2(nx + q10);
            prefetch_l2(nx + q11);
        }
        const float v00 = __ldg(im + q00);
        const float v01 = __ldg(im + q01);
        const float v10 = __ldg(im + q10);
        const float v11 = __ldg(im + q11);
        const float top = fmaf(ax, v01 - v00, v00);
        const float bot = fmaf(ax, v11 - v10, v10);
        *ob = fmaf(ay, bot - top, top);
        im += NPIX;
        ob += NPIX;
    }
}

extern "C" void kernel_launch(void* const* d_in, const int* in_sizes, int n_in,
                              void* d_out, int out_size)
{
    const float* x  = (const float*)d_in[0];
    const float* cp = (const float*)d_in[1];
    float* out = (float*)d_out;

    bspline_kernel<<<NPIX / 256, 256>>>(x, cp, out);
}

// round 14
// speedup vs baseline: 1.3915x; 1.3915x over previous
#include <cuda_runtime.h>

// BSplineTransformation: x (16,3,1024,1024) f32, control_points (1,2,35,35) f32
// out = concat(transformed (16,3,1024,1024), deformation_field (2,1024,1024))

#define HH 1024
#define WW 1024
#define NPIX (HH*WW)
#define NB 16
#define NC 3
#define NIMG (NB*NC)
#define CP 35
#define CP2 (CP*CP)

// R6 structure (1 pixel/thread, all 48 images) + manual 2-stage software
// pipeline: batch m+1's 4 gathers are issued BEFORE batch m is consumed, so
// the ~500cy load latency overlaps the next batch's flight instead of being
// fully exposed every iteration.

__global__ __launch_bounds__(256, 6) void bspline_kernel(
    const float* __restrict__ x,
    const float* __restrict__ cp,
    float* __restrict__ out)
{
    __shared__ float scp[2*CP2];
    for (int t = threadIdx.x; t < 2*CP2; t += 256) scp[t] = cp[t];
    __syncthreads();

    const int p = blockIdx.x * 256 + threadIdx.x;
    const int i = p >> 10;
    const int j = p & 1023;

    const float gy = fmaf((float)i, 2.0f / 1023.0f, -1.0f);
    const float gx = fmaf((float)j, 2.0f / 1023.0f, -1.0f);

    // ---- deformation field: grid_sample(control_points, border, align_corners) ----
    const float cx = (gx + 1.0f) * 17.0f;
    const float cy = (gy + 1.0f) * 17.0f;
    float icx = fminf(fmaxf((cx + 1.0f) * 17.0f, 0.0f), 34.0f);
    float icy = fminf(fmaxf((cy + 1.0f) * 17.0f, 0.0f), 34.0f);
    const float fcx = floorf(icx);
    const float fcy = floorf(icy);
    const int cx0 = (int)fcx;
    const int cy0 = (int)fcy;
    const int cx1 = min(cx0 + 1, CP - 1);
    const int cy1 = min(cy0 + 1, CP - 1);
    const float wx = icx - fcx;
    const float wy = icy - fcy;

    const int o00 = cy0 * CP + cx0;
    const int o01 = cy0 * CP + cx1;
    const int o10 = cy1 * CP + cx0;
    const int o11 = cy1 * CP + cx1;

    const float t0 = fmaf(wx, scp[o01] - scp[o00], scp[o00]);
    const float b0 = fmaf(wx, scp[o11] - scp[o10], scp[o10]);
    const float d0 = fmaf(wy, b0 - t0, t0);
    const float t1 = fmaf(wx, scp[CP2+o01] - scp[CP2+o00], scp[CP2+o00]);
    const float b1 = fmaf(wx, scp[CP2+o11] - scp[CP2+o10], scp[CP2+o10]);
    const float d1 = fmaf(wy, b1 - t1, t1);

    {
        float* def = out + (long long)NIMG * NPIX;
        def[p]        = d0;
        def[NPIX + p] = d1;
    }

    // ---- main sample coords (shared by all 48 images) ----
    float sx = fminf(fmaxf((gx + d1 + 1.0f) * 511.5f, 0.0f), 1023.0f);
    float sy = fminf(fmaxf((gy + d0 + 1.0f) * 511.5f, 0.0f), 1023.0f);
    const float fsx = floorf(sx);
    const float fsy = floorf(sy);
    const int ix0 = (int)fsx;
    const int iy0 = (int)fsy;
    const int ix1 = min(ix0 + 1, WW - 1);
    const int iy1 = min(iy0 + 1, HH - 1);
    const float ax = sx - fsx;
    const float ay = sy - fsy;

    const int q00 = (iy0 << 10) + ix0;
    const int q01 = (iy0 << 10) + ix1;
    const int q10 = (iy1 << 10) + ix0;
    const int q11 = (iy1 << 10) + ix1;

    // ---- 48 images, 2-stage software pipeline ----
    const float* im = x;
    float*       ob = out + p;

    // prologue: batch 0 in flight
    float a00 = __ldg(im + q00);
    float a01 = __ldg(im + q01);
    float a10 = __ldg(im + q10);
    float a11 = __ldg(im + q11);

    #pragma unroll
    for (int m = 0; m < NIMG; m += 2) {
        // issue batch m+1 (always exists: NIMG even)
        const float* im1 = im + NPIX;
        const float b00 = __ldg(im1 + q00);
        const float b01 = __ldg(im1 + q01);
        const float b10 = __ldg(im1 + q10);
        const float b11 = __ldg(im1 + q11);

        // consume batch m
        {
            const float top = fmaf(ax, a01 - a00, a00);
            const float bot = fmaf(ax, a11 - a10, a10);
            *ob = fmaf(ay, bot - top, top);
        }

        // issue batch m+2 (if any) while batch m+1 is still in flight
        if (m + 2 < NIMG) {
            const float* im2 = im + 2 * NPIX;
            a00 = __ldg(im2 + q00);
            a01 = __ldg(im2 + q01);
            a10 = __ldg(im2 + q10);
            a11 = __ldg(im2 + q11);
        }

        // consume batch m+1
        {
            const float top = fmaf(ax, b01 - b00, b00);
            const float bot = fmaf(ax, b11 - b10, b10);
            ob[NPIX] = fmaf(ay, bot - top, top);
        }

        im += 2 * NPIX;
        ob += 2 * NPIX;
    }
}

extern "C" void kernel_launch(void* const* d_in, const int* in_sizes, int n_in,
                              void* d_out, int out_size)
{
    const float* x  = (const float*)d_in[0];
    const float* cp = (const float*)d_in[1];
    float* out = (float*)d_out;

    bspline_kernel<<<NPIX / 256, 256>>>(x, cp, out);
}